// round 2
// baseline (speedup 1.0000x reference)
#include <cuda_runtime.h>
#include <cstdint>

// Problem constants
#define BATCH 128
#define TT    512
#define HID   1024
#define OUTW  256
#define NBLK  128      // persistent grid size (<=148 SMs, all co-resident)
#define NTHR  128      // 4 warps per CTA

// ---------------- device scratch (static, allocation-free) ----------------
__device__ __align__(16) float g_z[BATCH * HID];           // fc output
__device__ __align__(16) float g_h1[2][BATCH * HID];       // layer-0 hidden, double-buffered
__device__ __align__(16) float g_h2[2][BATCH * HID];       // layer-1 hidden, double-buffered
__device__ unsigned g_bar_count;
__device__ volatile unsigned g_bar_gen;

// ---------------- helpers ----------------
__device__ __forceinline__ unsigned f2tf32(float x) {
    unsigned r;
    asm("cvt.rna.tf32.f32 %0, %1;" : "=r"(r) : "f"(x));
    return r;
}

__device__ __forceinline__ void mma_tf32(float c[4], const unsigned a[4],
                                         unsigned b0, unsigned b1) {
    asm volatile(
        "mma.sync.aligned.m16n8k8.row.col.f32.tf32.tf32.f32 "
        "{%0,%1,%2,%3}, {%4,%5,%6,%7}, {%8,%9}, {%0,%1,%2,%3};"
        : "+f"(c[0]), "+f"(c[1]), "+f"(c[2]), "+f"(c[3])
        : "r"(a[0]), "r"(a[1]), "r"(a[2]), "r"(a[3]), "r"(b0), "r"(b1));
}

__device__ __forceinline__ float sigf(float x) { return 1.0f / (1.0f + __expf(-x)); }
__device__ __forceinline__ float tanh_fast(float x) {
    float e = __expf(2.0f * x);
    return 1.0f - 2.0f / (e + 1.0f);   // safe at +/-inf
}

// ---------------- software grid barrier (all NBLK CTAs resident) ----------------
__device__ __forceinline__ void grid_barrier() {
    __threadfence();                   // each thread's writes visible device-wide
    __syncthreads();
    if (threadIdx.x == 0) {
        unsigned gen = g_bar_gen;
        if (atomicAdd(&g_bar_count, 1u) == NBLK - 1) {
            *(volatile unsigned*)&g_bar_count = 0;
            __threadfence();
            g_bar_gen = gen + 1;
        } else {
            while (g_bar_gen == gen) { __nanosleep(32); }
        }
        __threadfence();
    }
    __syncthreads();
}

// ---------------- init ----------------
__global__ void init_zero_kernel() {
    int idx = blockIdx.x * 256 + threadIdx.x;   // 2048 blocks -> 524288
    if (idx < BATCH * HID * 2) {
        (&g_h1[0][0])[idx] = 0.0f;
        (&g_h2[0][0])[idx] = 0.0f;
    }
    if (idx == 0) { g_bar_count = 0; g_bar_gen = 0; }
}

// ---------------- fc: z = x @ fc_w^T + fc_b ----------------
__global__ void fc_kernel(const float* __restrict__ x, const float* __restrict__ fcw,
                          const float* __restrict__ fcb) {
    int idx = blockIdx.x * 256 + threadIdx.x;   // b*1024 + i, 131072 total
    int b = idx >> 10, i = idx & 1023;
    const float4* xr = reinterpret_cast<const float4*>(x + b * OUTW);
    const float4* wr = reinterpret_cast<const float4*>(fcw + i * OUTW);
    float s = fcb[i];
    #pragma unroll 8
    for (int o = 0; o < OUTW / 4; o++) {
        float4 xv = __ldg(xr + o), wv = __ldg(wr + o);
        s += xv.x * wv.x + xv.y * wv.y + xv.z * wv.z + xv.w * wv.w;
    }
    g_z[idx] = s;
}

// ---------------- tf32 GEMM tile phase: acc[64x64] += A[64xK] @ B^T ----------------
// A: activations (pitch 1024, read via .cg), rows mb*64..; A0 for k<1024, A1 for k>=1024.
// B: weights (pitch 1024); B0 for k<1024, B1 else. CTA gate-tile: n = gate*16 + jloc,
// W row = gate*1024 + nb*16 + jloc. Smem pitch 36 words: conflict-free STS.128 + LDS.32.
#define SPITCH 36
__device__ __forceinline__ void gemm_phase(
    float acc[8][4],
    const float* __restrict__ A0, const float* __restrict__ A1,
    const float* __restrict__ B0, const float* __restrict__ B1,
    int nIter, int mb, int nb,
    unsigned* As, unsigned* Bs)
{
    const int tid  = threadIdx.x;
    const int warp = tid >> 5, lane = tid & 31;
    const int grp  = lane >> 2, tig = lane & 3;

    #pragma unroll
    for (int f = 0; f < 8; f++)
        #pragma unroll
        for (int r = 0; r < 4; r++) acc[f][r] = 0.0f;

    float4 ra[4], rb[4];

    // prefetch iteration 0
    {
        const float* A = A0; const float* B = B0;
        #pragma unroll
        for (int v = 0; v < 4; v++) {
            int fid = tid + v * 128;
            int row = fid >> 3, k4 = (fid & 7) << 2;
            ra[v] = __ldcg(reinterpret_cast<const float4*>(A + (mb * 64 + row) * 1024 + k4));
            int wr = ((row >> 4) << 10) + nb * 16 + (row & 15);
            rb[v] = __ldg(reinterpret_cast<const float4*>(B + wr * 1024 + k4));
        }
    }

    for (int it = 0; it < nIter; it++) {
        // stage current tile (cvt to tf32)
        #pragma unroll
        for (int v = 0; v < 4; v++) {
            int fid = tid + v * 128;
            int row = fid >> 3, k4 = (fid & 7) << 2;
            uint4 ua = make_uint4(f2tf32(ra[v].x), f2tf32(ra[v].y), f2tf32(ra[v].z), f2tf32(ra[v].w));
            *reinterpret_cast<uint4*>(&As[row * SPITCH + k4]) = ua;
            uint4 ub = make_uint4(f2tf32(rb[v].x), f2tf32(rb[v].y), f2tf32(rb[v].z), f2tf32(rb[v].w));
            *reinterpret_cast<uint4*>(&Bs[row * SPITCH + k4]) = ub;
        }
        __syncthreads();

        // prefetch next tile into registers (overlaps with mma below)
        if (it + 1 < nIter) {
            int k = (it + 1) * 32;
            const float* A = (k < 1024) ? A0 : A1;
            const float* B = (k < 1024) ? B0 : B1;
            int kk = k & 1023;
            #pragma unroll
            for (int v = 0; v < 4; v++) {
                int fid = tid + v * 128;
                int row = fid >> 3, k4 = (fid & 7) << 2;
                ra[v] = __ldcg(reinterpret_cast<const float4*>(A + (mb * 64 + row) * 1024 + kk + k4));
                int wr = ((row >> 4) << 10) + nb * 16 + (row & 15);
                rb[v] = __ldg(reinterpret_cast<const float4*>(B + wr * 1024 + kk + k4));
            }
        }

        // compute on staged tile
        #pragma unroll
        for (int k8 = 0; k8 < 4; k8++) {
            unsigned a[4];
            int ar = warp * 16 + grp;
            int kc = k8 * 8 + tig;
            a[0] = As[ar * SPITCH + kc];
            a[1] = As[(ar + 8) * SPITCH + kc];
            a[2] = As[ar * SPITCH + kc + 4];
            a[3] = As[(ar + 8) * SPITCH + kc + 4];
            #pragma unroll
            for (int f = 0; f < 8; f++) {
                unsigned b0 = Bs[(f * 8 + grp) * SPITCH + kc];
                unsigned b1 = Bs[(f * 8 + grp) * SPITCH + kc + 4];
                mma_tf32(acc[f], a, b0, b1);
            }
        }
        __syncthreads();
    }
}

// ---------------- persistent LSTM kernel ----------------
__global__ void __launch_bounds__(NTHR, 1)
lstm_persistent(const float* __restrict__ Wih0, const float* __restrict__ Whh0,
                const float* __restrict__ bih0, const float* __restrict__ bhh0,
                const float* __restrict__ Wih1, const float* __restrict__ Whh1,
                const float* __restrict__ bih1, const float* __restrict__ bhh1,
                float* __restrict__ out)
{
    __shared__ unsigned As[64 * SPITCH];
    __shared__ unsigned Bs[64 * SPITCH];

    const int tid  = threadIdx.x;
    const int warp = tid >> 5, lane = tid & 31;
    const int grp  = lane >> 2, tig = lane & 3;
    const int mb = blockIdx.x & 1;        // batch block (2 x 64)
    const int nb = blockIdx.x >> 1;       // gate-column block (64 x 16 j's)

    float acc[8][4];
    float gx[8][4];                       // layer-0 input gates + biases (time-constant)
    float b1r[8][2];                      // layer-1 biases per (frag, col)
    float c1r[8], c2r[8];
    #pragma unroll
    for (int i = 0; i < 8; i++) { c1r[i] = 0.0f; c2r[i] = 0.0f; }

    // prologue: gx0 = z @ Wih0^T + bih0 + bhh0 (kept in registers for all 512 steps)
    gemm_phase(acc, g_z, g_z, Wih0, Wih0, 32, mb, nb, As, Bs);
    #pragma unroll
    for (int f = 0; f < 8; f++)
        #pragma unroll
        for (int r = 0; r < 4; r++) {
            int c = r & 1;
            int n = ((f >> 1) << 10) + nb * 16 + ((f & 1) << 3) + 2 * tig + c;
            gx[f][r] = acc[f][r] + __ldg(bih0 + n) + __ldg(bhh0 + n);
        }
    #pragma unroll
    for (int f = 0; f < 8; f++)
        #pragma unroll
        for (int c = 0; c < 2; c++) {
            int n = ((f >> 1) << 10) + nb * 16 + ((f & 1) << 3) + 2 * tig + c;
            b1r[f][c] = __ldg(bih1 + n) + __ldg(bhh1 + n);
        }

    for (int t = 0; t < TT; t++) {
        const int q = t & 1, p = q ^ 1;

        // layer 0 recurrence: h1_prev @ Whh0^T (+gx0) -> h1[q], c1 (registers)
        gemm_phase(acc, g_h1[p], g_h1[p], Whh0, Whh0, 32, mb, nb, As, Bs);
        #pragma unroll
        for (int rh = 0; rh < 2; rh++)
            #pragma unroll
            for (int b = 0; b < 2; b++)
                #pragma unroll
                for (int c = 0; c < 2; c++) {
                    int r = rh * 2 + c;
                    float si = acc[0 + b][r] + gx[0 + b][r];
                    float sf = acc[2 + b][r] + gx[2 + b][r];
                    float sg = acc[4 + b][r] + gx[4 + b][r];
                    float so = acc[6 + b][r] + gx[6 + b][r];
                    int cell = rh * 4 + b * 2 + c;
                    float cv = sigf(sf) * c1r[cell] + sigf(si) * tanh_fast(sg);
                    c1r[cell] = cv;
                    float h = sigf(so) * tanh_fast(cv);
                    int row = mb * 64 + warp * 16 + grp + rh * 8;
                    int j = nb * 16 + b * 8 + 2 * tig + c;
                    __stcg(&g_h1[q][row * 1024 + j], h);
                }

        grid_barrier();   // the single per-timestep sync (slot parity covers all other hazards)

        // layer 1: [h1[q] | h2[p]] @ [Wih1 | Whh1]^T -> h2[q], c2, output
        gemm_phase(acc, g_h1[q], g_h2[p], Wih1, Whh1, 64, mb, nb, As, Bs);
        #pragma unroll
        for (int rh = 0; rh < 2; rh++)
            #pragma unroll
            for (int b = 0; b < 2; b++)
                #pragma unroll
                for (int c = 0; c < 2; c++) {
                    int r = rh * 2 + c;
                    float si = acc[0 + b][r] + b1r[0 + b][c];
                    float sf = acc[2 + b][r] + b1r[2 + b][c];
                    float sg = acc[4 + b][r] + b1r[4 + b][c];
                    float so = acc[6 + b][r] + b1r[6 + b][c];
                    int cell = rh * 4 + b * 2 + c;
                    float cv = sigf(sf) * c2r[cell] + sigf(si) * tanh_fast(sg);
                    c2r[cell] = cv;
                    float h = sigf(so) * tanh_fast(cv);
                    int row = mb * 64 + warp * 16 + grp + rh * 8;
                    int j = nb * 16 + b * 8 + 2 * tig + c;
                    __stcg(&g_h2[q][row * 1024 + j], h);
                    out[(row * TT + t) * 1024 + j] = h;
                }
    }
}

// ---------------- launch ----------------
extern "C" void kernel_launch(void* const* d_in, const int* in_sizes, int n_in,
                              void* d_out, int out_size) {
    const float* x    = (const float*)d_in[0];
    const float* fc_w = (const float*)d_in[1];
    const float* fc_b = (const float*)d_in[2];
    const float* Wih0 = (const float*)d_in[3];
    const float* Whh0 = (const float*)d_in[4];
    const float* bih0 = (const float*)d_in[5];
    const float* bhh0 = (const float*)d_in[6];
    const float* Wih1 = (const float*)d_in[7];
    const float* Whh1 = (const float*)d_in[8];
    const float* bih1 = (const float*)d_in[9];
    const float* bhh1 = (const float*)d_in[10];
    float* out = (float*)d_out;

    init_zero_kernel<<<2048, 256>>>();
    fc_kernel<<<512, 256>>>(x, fc_w, fc_b);
    lstm_persistent<<<NBLK, NTHR>>>(Wih0, Whh0, bih0, bhh0,
                                    Wih1, Whh1, bih1, bhh1, out);
}

// round 3
// speedup vs baseline: 1.4687x; 1.4687x over previous
#include <cuda_runtime.h>
#include <cstdint>

// Problem constants
#define BATCH 128
#define TT    512
#define HID   1024
#define OUTW  256
#define NBLK  128      // persistent grid (all co-resident, <=148 SMs)
#define NTHR  256      // 8 warps
#define SPITCH 36      // smem row pitch in words (conflict-free, 16B-aligned)
#define TILEW  (64 * SPITCH)   // words per 64x32 tile buffer
#define NSTAGE 4

// ---------------- device scratch (static, allocation-free) ----------------
__device__ __align__(16) float g_z[BATCH * HID];         // fc output (tf32-rounded)
__device__ __align__(16) float g_h1[2][BATCH * HID];     // layer-0 hidden (tf32-rounded)
__device__ __align__(16) float g_h2[2][BATCH * HID];     // layer-1 hidden (tf32-rounded)
__device__ __align__(16) float g_wpack[4 * 64 * 32 * 64 * 32];  // packed tf32 weights, 64MB
__device__ unsigned g_bar_count;
__device__ volatile unsigned g_bar_gen;

// ---------------- helpers ----------------
__device__ __forceinline__ unsigned f2tf32(float x) {
    unsigned r;
    asm("cvt.rna.tf32.f32 %0, %1;" : "=r"(r) : "f"(x));
    return r;
}

__device__ __forceinline__ void mma_tf32(float c[4], const unsigned a[4],
                                         unsigned b0, unsigned b1) {
    asm volatile(
        "mma.sync.aligned.m16n8k8.row.col.f32.tf32.tf32.f32 "
        "{%0,%1,%2,%3}, {%4,%5,%6,%7}, {%8,%9}, {%0,%1,%2,%3};"
        : "+f"(c[0]), "+f"(c[1]), "+f"(c[2]), "+f"(c[3])
        : "r"(a[0]), "r"(a[1]), "r"(a[2]), "r"(a[3]), "r"(b0), "r"(b1));
}

__device__ __forceinline__ void cp16(unsigned dst, const void* src) {
    asm volatile("cp.async.cg.shared.global [%0], [%1], 16;\n" :: "r"(dst), "l"(src));
}
#define CP_COMMIT() asm volatile("cp.async.commit_group;\n" ::: "memory")
#define CP_WAIT2()  asm volatile("cp.async.wait_group 2;\n" ::: "memory")

__device__ __forceinline__ float sigf(float x) { return 1.0f / (1.0f + __expf(-x)); }
__device__ __forceinline__ float tanh_fast(float x) {
    float e = __expf(2.0f * x);
    return 1.0f - 2.0f / (e + 1.0f);
}

// ---------------- software grid barrier ----------------
__device__ __forceinline__ void grid_barrier() {
    __threadfence();
    __syncthreads();
    if (threadIdx.x == 0) {
        unsigned gen = g_bar_gen;
        if (atomicAdd(&g_bar_count, 1u) == NBLK - 1) {
            *(volatile unsigned*)&g_bar_count = 0;
            __threadfence();
            g_bar_gen = gen + 1;
        } else {
            while (g_bar_gen == gen) { __nanosleep(32); }
        }
        __threadfence();
    }
    __syncthreads();
}

// ---------------- init ----------------
__global__ void init_zero_kernel() {
    int idx = blockIdx.x * 256 + threadIdx.x;   // 2048 blocks -> 524288
    if (idx < BATCH * HID * 2) {
        (&g_h1[0][0])[idx] = 0.0f;
        (&g_h2[0][0])[idx] = 0.0f;
    }
    if (idx == 0) { g_bar_count = 0; g_bar_gen = 0; }
}

// ---------------- weight pre-pack: tf32, GEMM-tile-native layout ----------------
// wpack[mat][nb][kc][rr][kk]; tile column rr: gate=(rr>>3)&3, jloc=(rr&7)+((rr>>5)<<3);
// source row = gate*1024 + nb*16 + jloc, col = kc*32 + kk.
__global__ void pack_kernel(const float* __restrict__ W0, const float* __restrict__ W1,
                            const float* __restrict__ W2, const float* __restrict__ W3) {
    int idx = blockIdx.x * 256 + threadIdx.x;   // 65536 blocks -> 16777216
    int kk = idx & 31;
    int rr = (idx >> 5) & 63;
    int kc = (idx >> 11) & 31;
    int nb = (idx >> 16) & 63;
    int mat = idx >> 22;
    const float* W = (mat == 0) ? W0 : (mat == 1) ? W1 : (mat == 2) ? W2 : W3;
    int gate = (rr >> 3) & 3;
    int jloc = (rr & 7) + ((rr >> 5) << 3);
    int srow = gate * 1024 + nb * 16 + jloc;
    float v = W[srow * 1024 + kc * 32 + kk];
    g_wpack[idx] = __uint_as_float(f2tf32(v));
}

// ---------------- fc: z = x @ fc_w^T + fc_b (stored tf32-rounded) ----------------
__global__ void fc_kernel(const float* __restrict__ x, const float* __restrict__ fcw,
                          const float* __restrict__ fcb) {
    int idx = blockIdx.x * 256 + threadIdx.x;   // b*1024 + i
    int b = idx >> 10, i = idx & 1023;
    const float4* xr = reinterpret_cast<const float4*>(x + b * OUTW);
    const float4* wr = reinterpret_cast<const float4*>(fcw + i * OUTW);
    float s = fcb[i];
    #pragma unroll 8
    for (int o = 0; o < OUTW / 4; o++) {
        float4 xv = __ldg(xr + o), wv = __ldg(wr + o);
        s += xv.x * wv.x + xv.y * wv.y + xv.z * wv.z + xv.w * wv.w;
    }
    g_z[idx] = __uint_as_float(f2tf32(s));
}

// ---------------- GEMM phase: acc[64x64] += A[64xK] @ Bpacked^T ----------------
// 8 warps: wm=warp>>1 (16-row slice), wn=warp&1 (32-col slice).
// A: tf32-rounded activations, pitch 1024 floats; A0 for k<1024 else A1.
// B0/B1: packed bases for this nb (B1 used for k>=1024).
__device__ __forceinline__ void tile_compute(const unsigned* __restrict__ as,
                                             const unsigned* __restrict__ bs,
                                             float acc[4][4], int wm, int wn,
                                             int grp, int tig) {
    #pragma unroll
    for (int k8 = 0; k8 < 4; k8++) {
        int kc = k8 * 8 + tig;
        const unsigned* ar = as + (wm * 16 + grp) * SPITCH + kc;
        unsigned a[4];
        a[0] = ar[0];
        a[1] = ar[8 * SPITCH];
        a[2] = ar[4];
        a[3] = ar[8 * SPITCH + 4];
        #pragma unroll
        for (int j = 0; j < 4; j++) {
            const unsigned* br = bs + (wn * 32 + j * 8 + grp) * SPITCH + kc;
            mma_tf32(acc[j], a, br[0], br[4]);
        }
    }
}

__device__ __forceinline__ void gemm_phase(
    float acc[4][4],
    const float* __restrict__ A0, const float* __restrict__ A1,
    const float* __restrict__ B0, const float* __restrict__ B1,
    int nIter, int mb, unsigned* As, unsigned* Bs,
    unsigned AsBase, unsigned BsBase,
    int tid, int wm, int wn, int grp, int tig)
{
    #pragma unroll
    for (int j = 0; j < 4; j++)
        #pragma unroll
        for (int r = 0; r < 4; r++) acc[j][r] = 0.0f;

    const int row = (tid >> 3) & 63;          // reuse per-thread load coords
    const int row2 = ((tid + 256) >> 3) & 63; // second chunk row (row + 32)
    const int k4 = (tid & 7) << 2;

    // issue(s): stage s -> ring slot s&3
    #define ISSUE(s) do {                                                          \
        const float* A_ = ((s) < 32) ? A0 : A1;                                    \
        const float* Bt_ = (((s) < 32) ? B0 : B1) + ((s) & 31) * 2048;             \
        int kk_ = ((s) * 32) & 1023;                                               \
        unsigned so_ = ((s) & 3) * (TILEW * 4);                                    \
        cp16(AsBase + so_ + (row * SPITCH + k4) * 4,                               \
             A_ + (mb * 64 + row) * 1024 + kk_ + k4);                              \
        cp16(AsBase + so_ + (row2 * SPITCH + k4) * 4,                              \
             A_ + (mb * 64 + row2) * 1024 + kk_ + k4);                             \
        cp16(BsBase + so_ + (row * SPITCH + k4) * 4,  Bt_ + row * 32 + k4);        \
        cp16(BsBase + so_ + (row2 * SPITCH + k4) * 4, Bt_ + row2 * 32 + k4);       \
    } while (0)

    ISSUE(0); CP_COMMIT();
    ISSUE(1); CP_COMMIT();
    ISSUE(2); CP_COMMIT();

    for (int it = 0; it < nIter; it++) {
        CP_WAIT2();
        __syncthreads();
        tile_compute(As + (it & 3) * TILEW, Bs + (it & 3) * TILEW,
                     acc, wm, wn, grp, tig);
        if (it + 3 < nIter) ISSUE(it + 3);
        CP_COMMIT();
    }
    #undef ISSUE
}

// ---------------- persistent LSTM kernel ----------------
__global__ void __launch_bounds__(NTHR, 1)
lstm_persistent(const float* __restrict__ bih0, const float* __restrict__ bhh0,
                const float* __restrict__ bih1, const float* __restrict__ bhh1,
                float* __restrict__ out)
{
    extern __shared__ unsigned sh[];
    unsigned* As = sh;
    unsigned* Bs = sh + NSTAGE * TILEW;
    const unsigned AsBase = (unsigned)__cvta_generic_to_shared(As);
    const unsigned BsBase = (unsigned)__cvta_generic_to_shared(Bs);

    const int tid  = threadIdx.x;
    const int warp = tid >> 5, lane = tid & 31;
    const int grp  = lane >> 2, tig = lane & 3;
    const int wm   = warp >> 1, wn = warp & 1;
    const int mb = blockIdx.x & 1;        // batch block (2 x 64 rows)
    const int nb = blockIdx.x >> 1;       // 16-column block of j (0..63)

    const float* PB0 = g_wpack + (size_t)(0 * 64 + nb) * 65536;  // Wih0
    const float* PB1 = g_wpack + (size_t)(1 * 64 + nb) * 65536;  // Whh0
    const float* PB2 = g_wpack + (size_t)(2 * 64 + nb) * 65536;  // Wih1
    const float* PB3 = g_wpack + (size_t)(3 * 64 + nb) * 65536;  // Whh1

    float acc[4][4];
    float gx[4][4];        // layer-0 input gates + biases (time-constant, registers)
    float b1r[4][2];       // layer-1 bias sums
    float c1r[4], c2r[4];
    #pragma unroll
    for (int i = 0; i < 4; i++) { c1r[i] = 0.0f; c2r[i] = 0.0f; }

    // prologue: gx0 = z @ Wih0^T + bih0 + bhh0
    gemm_phase(acc, g_z, g_z, PB0, PB0, 32, mb, As, Bs, AsBase, BsBase,
               tid, wm, wn, grp, tig);
    #pragma unroll
    for (int g = 0; g < 4; g++)
        #pragma unroll
        for (int r = 0; r < 4; r++) {
            int n = g * 1024 + nb * 16 + wn * 8 + 2 * tig + (r & 1);
            gx[g][r] = acc[g][r] + __ldg(bih0 + n) + __ldg(bhh0 + n);
        }
    #pragma unroll
    for (int g = 0; g < 4; g++)
        #pragma unroll
        for (int c = 0; c < 2; c++) {
            int n = g * 1024 + nb * 16 + wn * 8 + 2 * tig + c;
            b1r[g][c] = __ldg(bih1 + n) + __ldg(bhh1 + n);
        }

    const int rowb = mb * 64 + wm * 16 + grp;          // this thread's base batch row
    const int jb   = nb * 16 + wn * 8 + 2 * tig;       // this thread's base j

    for (int t = 0; t < TT; t++) {
        const int q = t & 1, p = q ^ 1;

        // layer 0: h1_prev @ Whh0^T (+gx) -> h1[q], c1
        gemm_phase(acc, g_h1[p], g_h1[p], PB1, PB1, 32, mb, As, Bs, AsBase, BsBase,
                   tid, wm, wn, grp, tig);
        #pragma unroll
        for (int r = 0; r < 4; r++) {
            float si = acc[0][r] + gx[0][r];
            float sf = acc[1][r] + gx[1][r];
            float sg = acc[2][r] + gx[2][r];
            float so = acc[3][r] + gx[3][r];
            float cv = sigf(sf) * c1r[r] + sigf(si) * tanh_fast(sg);
            c1r[r] = cv;
            float h = sigf(so) * tanh_fast(cv);
            int row = rowb + ((r & 2) ? 8 : 0);
            int j = jb + (r & 1);
            __stcg(&g_h1[q][row * 1024 + j], __uint_as_float(f2tf32(h)));
        }

        grid_barrier();   // single per-timestep sync; slot parity covers remaining hazards

        // layer 1: [h1[q] | h2[p]] @ [Wih1 | Whh1]^T -> h2[q], c2, out
        gemm_phase(acc, g_h1[q], g_h2[p], PB2, PB3, 64, mb, As, Bs, AsBase, BsBase,
                   tid, wm, wn, grp, tig);
        #pragma unroll
        for (int r = 0; r < 4; r++) {
            float si = acc[0][r] + b1r[0][r & 1];
            float sf = acc[1][r] + b1r[1][r & 1];
            float sg = acc[2][r] + b1r[2][r & 1];
            float so = acc[3][r] + b1r[3][r & 1];
            float cv = sigf(sf) * c2r[r] + sigf(si) * tanh_fast(sg);
            c2r[r] = cv;
            float h = sigf(so) * tanh_fast(cv);
            int row = rowb + ((r & 2) ? 8 : 0);
            int j = jb + (r & 1);
            __stcg(&g_h2[q][row * 1024 + j], __uint_as_float(f2tf32(h)));
            out[((size_t)row * TT + t) * 1024 + j] = h;   // full-precision output
        }
    }
}

// ---------------- launch ----------------
extern "C" void kernel_launch(void* const* d_in, const int* in_sizes, int n_in,
                              void* d_out, int out_size) {
    const float* x    = (const float*)d_in[0];
    const float* fc_w = (const float*)d_in[1];
    const float* fc_b = (const float*)d_in[2];
    const float* Wih0 = (const float*)d_in[3];
    const float* Whh0 = (const float*)d_in[4];
    const float* bih0 = (const float*)d_in[5];
    const float* bhh0 = (const float*)d_in[6];
    const float* Wih1 = (const float*)d_in[7];
    const float* Whh1 = (const float*)d_in[8];
    const float* bih1 = (const float*)d_in[9];
    const float* bhh1 = (const float*)d_in[10];
    float* out = (float*)d_out;

    static int smem_set = 0;
    const int smem_bytes = 2 * NSTAGE * TILEW * 4;   // 73728
    if (!smem_set) {
        cudaFuncSetAttribute(lstm_persistent,
                             cudaFuncAttributeMaxDynamicSharedMemorySize, smem_bytes);
        smem_set = 1;
    }

    init_zero_kernel<<<2048, 256>>>();
    pack_kernel<<<65536, 256>>>(Wih0, Whh0, Wih1, Whh1);
    fc_kernel<<<512, 256>>>(x, fc_w, fc_b);
    lstm_persistent<<<NBLK, NTHR, smem_bytes>>>(bih0, bhh0, bih1, bhh1, out);
}

// round 4
// speedup vs baseline: 1.7563x; 1.1958x over previous
#include <cuda_runtime.h>
#include <cstdint>

// Problem constants
#define BATCH 128
#define TT    512
#define HID   1024
#define OUTW  256
#define NBLK  128      // persistent grid (all co-resident)
#define NTHR  256      // 8 warps
#define SPITCH 72      // smem row pitch in words (conflict-free LDS.64: 72/2 % 16 == 4)
#define TILEW  (64 * SPITCH)   // words per 64x64 tile buffer
#define NSTAGE 4

// ---------------- device scratch (static, allocation-free) ----------------
__device__ __align__(16) float g_z[BATCH * HID];         // fc output (tf32, k-permuted)
__device__ __align__(16) float g_h1[2][BATCH * HID];     // layer-0 hidden (tf32, k-permuted)
__device__ __align__(16) float g_h2[2][BATCH * HID];     // layer-1 hidden (tf32, k-permuted)
__device__ __align__(16) float g_wpack[4 * 64 * 16 * 64 * 64];  // packed tf32 weights, 64MB
__device__ unsigned g_bar_count;
__device__ volatile unsigned g_bar_gen;

// permutation of the low-3 bits: i=b2b1b0 -> ((i&3)<<1)|(i>>2); pairs (k,k+4) adjacent
__device__ __host__ __forceinline__ int perm8(int i) { return ((i & 3) << 1) | ((i >> 2) & 1); }

// ---------------- helpers ----------------
__device__ __forceinline__ unsigned f2tf32(float x) {
    unsigned r;
    asm("cvt.rna.tf32.f32 %0, %1;" : "=r"(r) : "f"(x));
    return r;
}

__device__ __forceinline__ void mma_tf32(float c[4], unsigned a0, unsigned a1,
                                         unsigned a2, unsigned a3,
                                         unsigned b0, unsigned b1) {
    asm volatile(
        "mma.sync.aligned.m16n8k8.row.col.f32.tf32.tf32.f32 "
        "{%0,%1,%2,%3}, {%4,%5,%6,%7}, {%8,%9}, {%0,%1,%2,%3};"
        : "+f"(c[0]), "+f"(c[1]), "+f"(c[2]), "+f"(c[3])
        : "r"(a0), "r"(a1), "r"(a2), "r"(a3), "r"(b0), "r"(b1));
}

__device__ __forceinline__ void cp16(unsigned dst, const void* src) {
    asm volatile("cp.async.cg.shared.global [%0], [%1], 16;\n" :: "r"(dst), "l"(src));
}
#define CP_COMMIT() asm volatile("cp.async.commit_group;\n" ::: "memory")
#define CP_WAIT2()  asm volatile("cp.async.wait_group 2;\n" ::: "memory")

__device__ __forceinline__ float sigf(float x) { return 1.0f / (1.0f + __expf(-x)); }
__device__ __forceinline__ float tanh_fast(float x) {
    float e = __expf(2.0f * x);
    return 1.0f - 2.0f / (e + 1.0f);
}

// ---------------- software grid barrier (pure spin) ----------------
__device__ __forceinline__ void grid_barrier() {
    __threadfence();
    __syncthreads();
    if (threadIdx.x == 0) {
        unsigned gen = g_bar_gen;
        if (atomicAdd(&g_bar_count, 1u) == NBLK - 1) {
            *(volatile unsigned*)&g_bar_count = 0;
            __threadfence();
            g_bar_gen = gen + 1;
        } else {
            while (g_bar_gen == gen) {}
        }
        __threadfence();
    }
    __syncthreads();
}

// ---------------- init ----------------
__global__ void init_zero_kernel() {
    int idx = blockIdx.x * 256 + threadIdx.x;
    if (idx < BATCH * HID * 2) {
        (&g_h1[0][0])[idx] = 0.0f;
        (&g_h2[0][0])[idx] = 0.0f;
    }
    if (idx == 0) { g_bar_count = 0; g_bar_gen = 0; }
}

// ---------------- weight pre-pack: tf32, tile-native, k-permuted ----------------
// layout: wpack[mat][nb][kc16][rr64][kk64]; rr: gate=(rr>>3)&3, jloc=(rr&7)+((rr>>5)<<3)
__global__ void pack_kernel(const float* __restrict__ W0, const float* __restrict__ W1,
                            const float* __restrict__ W2, const float* __restrict__ W3) {
    int idx = blockIdx.x * 256 + threadIdx.x;   // 65536 blocks
    int kk  = idx & 63;
    int rr  = (idx >> 6) & 63;
    int kc  = (idx >> 12) & 15;
    int nb  = (idx >> 16) & 63;
    int mat = idx >> 22;
    const float* W = (mat == 0) ? W0 : (mat == 1) ? W1 : (mat == 2) ? W2 : W3;
    int gate = (rr >> 3) & 3;
    int jloc = (rr & 7) + ((rr >> 5) << 3);
    int srow = gate * 1024 + nb * 16 + jloc;
    float v = W[srow * 1024 + kc * 64 + kk];
    int kkp = (kk & ~7) | perm8(kk & 7);
    g_wpack[(((size_t)(mat * 64 + nb) * 16 + kc) << 12) + rr * 64 + kkp] =
        __uint_as_float(f2tf32(v));
}

// ---------------- fc: z = x @ fc_w^T + fc_b (tf32, k-permuted store) ----------------
__global__ void fc_kernel(const float* __restrict__ x, const float* __restrict__ fcw,
                          const float* __restrict__ fcb) {
    int idx = blockIdx.x * 256 + threadIdx.x;   // b*1024 + i
    int b = idx >> 10, i = idx & 1023;
    const float4* xr = reinterpret_cast<const float4*>(x + b * OUTW);
    const float4* wr = reinterpret_cast<const float4*>(fcw + i * OUTW);
    float s = fcb[i];
    #pragma unroll 8
    for (int o = 0; o < OUTW / 4; o++) {
        float4 xv = __ldg(xr + o), wv = __ldg(wr + o);
        s += xv.x * wv.x + xv.y * wv.y + xv.z * wv.z + xv.w * wv.w;
    }
    int ip = (i & ~7) | perm8(i & 7);
    g_z[b * 1024 + ip] = __uint_as_float(f2tf32(s));
}

// ---------------- tile compute: acc[16x32 per warp] += A64x64 @ B64x64^T ----------------
__device__ __forceinline__ void tile_compute(const unsigned* __restrict__ as,
                                             const unsigned* __restrict__ bs,
                                             float acc[4][4], int wm, int wn,
                                             int grp, int tig) {
    const unsigned* pa = as + (wm * 16 + grp) * SPITCH + 2 * tig;
    const unsigned* pb = bs + (wn * 32 + grp) * SPITCH + 2 * tig;

    uint2 a0 = *(const uint2*)pa;
    uint2 a1 = *(const uint2*)(pa + 8 * SPITCH);
    uint2 b0 = *(const uint2*)pb;
    uint2 b1 = *(const uint2*)(pb + 8 * SPITCH);
    uint2 b2 = *(const uint2*)(pb + 16 * SPITCH);
    uint2 b3 = *(const uint2*)(pb + 24 * SPITCH);

    #pragma unroll
    for (int k8 = 0; k8 < 8; k8++) {
        uint2 na0, na1, nb0, nb1, nb2, nb3;
        if (k8 < 7) {
            const unsigned* qa = pa + (k8 + 1) * 8;
            const unsigned* qb = pb + (k8 + 1) * 8;
            na0 = *(const uint2*)qa;
            na1 = *(const uint2*)(qa + 8 * SPITCH);
            nb0 = *(const uint2*)qb;
            nb1 = *(const uint2*)(qb + 8 * SPITCH);
            nb2 = *(const uint2*)(qb + 16 * SPITCH);
            nb3 = *(const uint2*)(qb + 24 * SPITCH);
        }
        mma_tf32(acc[0], a0.x, a1.x, a0.y, a1.y, b0.x, b0.y);
        mma_tf32(acc[1], a0.x, a1.x, a0.y, a1.y, b1.x, b1.y);
        mma_tf32(acc[2], a0.x, a1.x, a0.y, a1.y, b2.x, b2.y);
        mma_tf32(acc[3], a0.x, a1.x, a0.y, a1.y, b3.x, b3.y);
        if (k8 < 7) {
            a0 = na0; a1 = na1; b0 = nb0; b1 = nb1; b2 = nb2; b3 = nb3;
        }
    }
}

// ---------------- GEMM phase: acc += A[64 x 64*nIter] @ Bpacked^T ----------------
__device__ __forceinline__ void gemm_phase(
    float acc[4][4],
    const float* __restrict__ A0, const float* __restrict__ A1,
    const float* __restrict__ B0, const float* __restrict__ B1,
    int nIter, int mb, unsigned* As, unsigned* Bs,
    unsigned AsBase, unsigned BsBase,
    int tid, int wm, int wn, int grp, int tig)
{
    #pragma unroll
    for (int j = 0; j < 4; j++)
        #pragma unroll
        for (int r = 0; r < 4; r++) acc[j][r] = 0.0f;

    const int lrow = tid >> 4;            // 0..15 base row, +16 per v
    const int c4   = (tid & 15) << 2;     // 0..60

    #define ISSUE(s) do {                                                           \
        const float* A_  = ((s) < 16) ? A0 : A1;                                    \
        const float* Bt_ = (((s) < 16) ? B0 : B1) + (((s) & 15) << 12);             \
        int kk_ = ((s) * 64) & 1023;                                                \
        unsigned so_ = ((s) & 3) * (TILEW * 4);                                     \
        _Pragma("unroll")                                                           \
        for (int v = 0; v < 4; v++) {                                               \
            int row = lrow + v * 16;                                                \
            cp16(AsBase + so_ + (row * SPITCH + c4) * 4,                            \
                 A_ + (mb * 64 + row) * 1024 + kk_ + c4);                           \
            cp16(BsBase + so_ + (row * SPITCH + c4) * 4, Bt_ + row * 64 + c4);      \
        }                                                                           \
    } while (0)

    ISSUE(0); CP_COMMIT();
    ISSUE(1); CP_COMMIT();
    ISSUE(2); CP_COMMIT();

    for (int it = 0; it < nIter; it++) {
        CP_WAIT2();
        __syncthreads();
        tile_compute(As + (it & 3) * TILEW, Bs + (it & 3) * TILEW,
                     acc, wm, wn, grp, tig);
        if (it + 3 < nIter) ISSUE(it + 3);
        CP_COMMIT();
    }
    #undef ISSUE
}

// ---------------- persistent LSTM kernel ----------------
__global__ void __launch_bounds__(NTHR, 1)
lstm_persistent(const float* __restrict__ bih0, const float* __restrict__ bhh0,
                const float* __restrict__ bih1, const float* __restrict__ bhh1,
                float* __restrict__ out)
{
    extern __shared__ unsigned sh[];
    unsigned* As = sh;
    unsigned* Bs = sh + NSTAGE * TILEW;
    const unsigned AsBase = (unsigned)__cvta_generic_to_shared(As);
    const unsigned BsBase = (unsigned)__cvta_generic_to_shared(Bs);

    const int tid  = threadIdx.x;
    const int warp = tid >> 5, lane = tid & 31;
    const int grp  = lane >> 2, tig = lane & 3;
    const int wm   = warp >> 1, wn = warp & 1;
    const int mb = blockIdx.x & 1;        // batch block (2 x 64 rows)
    const int nb = blockIdx.x >> 1;       // 16-column block of j (0..63)

    const float* PB0 = g_wpack + (size_t)(0 * 64 + nb) * 65536;  // Wih0
    const float* PB1 = g_wpack + (size_t)(1 * 64 + nb) * 65536;  // Whh0
    const float* PB2 = g_wpack + (size_t)(2 * 64 + nb) * 65536;  // Wih1
    const float* PB3 = g_wpack + (size_t)(3 * 64 + nb) * 65536;  // Whh1

    float acc[4][4];
    float gx[4][4];        // layer-0 input gates + biases (time-constant)
    float b1r[4][2];       // layer-1 bias sums
    float c1r[4], c2r[4];
    #pragma unroll
    for (int i = 0; i < 4; i++) { c1r[i] = 0.0f; c2r[i] = 0.0f; }

    // prologue: gx0 = z @ Wih0^T + bih0 + bhh0
    gemm_phase(acc, g_z, g_z, PB0, PB0, 16, mb, As, Bs, AsBase, BsBase,
               tid, wm, wn, grp, tig);
    #pragma unroll
    for (int g = 0; g < 4; g++)
        #pragma unroll
        for (int r = 0; r < 4; r++) {
            int n = g * 1024 + nb * 16 + wn * 8 + 2 * tig + (r & 1);
            gx[g][r] = acc[g][r] + __ldg(bih0 + n) + __ldg(bhh0 + n);
        }
    #pragma unroll
    for (int g = 0; g < 4; g++)
        #pragma unroll
        for (int c = 0; c < 2; c++) {
            int n = g * 1024 + nb * 16 + wn * 8 + 2 * tig + c;
            b1r[g][c] = __ldg(bih1 + n) + __ldg(bhh1 + n);
        }

    const int rowb = mb * 64 + wm * 16 + grp;          // base batch row
    const int jb   = nb * 16 + wn * 8;                 // 8-col group base (logical)

    for (int t = 0; t < TT; t++) {
        const int q = t & 1, p = q ^ 1;

        // layer 0: h1_prev @ Whh0^T (+gx) -> h1[q], c1
        gemm_phase(acc, g_h1[p], g_h1[p], PB1, PB1, 16, mb, As, Bs, AsBase, BsBase,
                   tid, wm, wn, grp, tig);
        #pragma unroll
        for (int r = 0; r < 4; r++) {
            float si = acc[0][r] + gx[0][r];
            float sf = acc[1][r] + gx[1][r];
            float sg = acc[2][r] + gx[2][r];
            float so = acc[3][r] + gx[3][r];
            float cv = sigf(sf) * c1r[r] + sigf(si) * tanh_fast(sg);
            c1r[r] = cv;
            float h = sigf(so) * tanh_fast(cv);
            int row = rowb + ((r & 2) ? 8 : 0);
            int i3 = 2 * tig + (r & 1);
            __stcg(&g_h1[q][row * 1024 + jb + perm8(i3)], __uint_as_float(f2tf32(h)));
        }

        grid_barrier();   // single per-timestep sync; slot parity covers other hazards

        // layer 1: [h1[q] | h2[p]] @ [Wih1 | Whh1]^T -> h2[q], c2, out
        gemm_phase(acc, g_h1[q], g_h2[p], PB2, PB3, 32, mb, As, Bs, AsBase, BsBase,
                   tid, wm, wn, grp, tig);
        #pragma unroll
        for (int r = 0; r < 4; r++) {
            float si = acc[0][r] + b1r[0][r & 1];
            float sf = acc[1][r] + b1r[1][r & 1];
            float sg = acc[2][r] + b1r[2][r & 1];
            float so = acc[3][r] + b1r[3][r & 1];
            float cv = sigf(sf) * c2r[r] + sigf(si) * tanh_fast(sg);
            c2r[r] = cv;
            float h = sigf(so) * tanh_fast(cv);
            int row = rowb + ((r & 2) ? 8 : 0);
            int i3 = 2 * tig + (r & 1);
            __stcg(&g_h2[q][row * 1024 + jb + perm8(i3)], __uint_as_float(f2tf32(h)));
            out[((size_t)row * TT + t) * 1024 + jb + i3] = h;   // full-precision output
        }
    }
}

// ---------------- launch ----------------
extern "C" void kernel_launch(void* const* d_in, const int* in_sizes, int n_in,
                              void* d_out, int out_size) {
    const float* x    = (const float*)d_in[0];
    const float* fc_w = (const float*)d_in[1];
    const float* fc_b = (const float*)d_in[2];
    const float* Wih0 = (const float*)d_in[3];
    const float* Whh0 = (const float*)d_in[4];
    const float* bih0 = (const float*)d_in[5];
    const float* bhh0 = (const float*)d_in[6];
    const float* Wih1 = (const float*)d_in[7];
    const float* Whh1 = (const float*)d_in[8];
    const float* bih1 = (const float*)d_in[9];
    const float* bhh1 = (const float*)d_in[10];
    float* out = (float*)d_out;

    static int smem_set = 0;
    const int smem_bytes = 2 * NSTAGE * TILEW * 4;   // 147456
    if (!smem_set) {
        cudaFuncSetAttribute(lstm_persistent,
                             cudaFuncAttributeMaxDynamicSharedMemorySize, smem_bytes);
        smem_set = 1;
    }

    init_zero_kernel<<<2048, 256>>>();
    pack_kernel<<<65536, 256>>>(Wih0, Whh0, Wih1, Whh1);
    fc_kernel<<<512, 256>>>(x, fc_w, fc_b);
    lstm_persistent<<<NBLK, NTHR, smem_bytes>>>(bih0, bhh0, bih1, bhh1, out);
}